// round 2
// baseline (speedup 1.0000x reference)
#include <cuda_runtime.h>

#define N_ 128
#define D_ 512
#define L_ 512
#define K_ 512
#define M_ (N_*D_)   // 65536

#define BM 128
#define BN 64
#define BK 16
#define TM 8
#define TN 4
#define THREADS 256

// Scratch (static device allocations are allowed; no runtime mallocs)
__device__ float g_Bc[L_*K_];     // cos basis  [L][K]
__device__ float g_Bs[L_*K_];     // sin basis  [L][K]
__device__ float g_scale[D_*L_];  // window*exp [D][L]

// ---------------------------------------------------------------------------
// Prep: basis + per-(d,l) scale. Double-precision sincos so accuracy survives
// --use_fast_math (args up to ~3211 rad). Angle construction mirrors the
// reference's fp32 rounding: ang = fp32(2pi/511) * fp32(l*k).
// ---------------------------------------------------------------------------
__global__ void prep_kernel(const float* __restrict__ a,
                            const float* __restrict__ sigma) {
    int idx = blockIdx.x * blockDim.x + threadIdx.x;
    if (idx >= L_*K_) return;
    int i = idx / K_;   // l (basis) / d (scale)
    int j = idx % K_;   // k (basis) / l (scale)

    const float TWOPI = 6.28318530717958647692f;

    // DFT basis
    float c0   = __fdiv_rn(TWOPI, 511.0f);
    float angf = c0 * (float)(i * j);          // exact int product, fp32 mul
    double s, c;
    sincos((double)angf, &s, &c);
    g_Bc[idx] = (float)c;
    g_Bs[idx] = (float)s;

    // scale[d=i][l=j] = (a - (1-a) cos(2*pi*l/511)) * exp(sigma/511)
    float wang = __fdiv_rn((float)j * TWOPI, 511.0f);
    float wcos = (float)cos((double)wang);
    float ad   = a[i];
    float w    = ad - (1.0f - ad) * wcos;
    float e    = expf(__fdiv_rn(sigma[i], 511.0f));
    g_scale[idx] = w * e;
}

// ---------------------------------------------------------------------------
// f32x2 packed-FMA helpers (sm_100+): 2 IEEE-RN fp32 FMAs per instruction.
// ---------------------------------------------------------------------------
__device__ __forceinline__ unsigned long long pack2(float x, float y) {
    unsigned long long r;
    asm("mov.b64 %0, {%1, %2};" : "=l"(r) : "f"(x), "f"(y));
    return r;
}
__device__ __forceinline__ void unpack2(unsigned long long v, float& x, float& y) {
    asm("mov.b64 {%0, %1}, %2;" : "=f"(x), "=f"(y) : "l"(v));
}
__device__ __forceinline__ unsigned long long fma2(unsigned long long a,
                                                   unsigned long long b,
                                                   unsigned long long c) {
    unsigned long long d;
    asm("fma.rn.f32x2 %0, %1, %2, %3;" : "=l"(d) : "l"(a), "l"(b), "l"(c));
    return d;
}

// ---------------------------------------------------------------------------
// Fused GEMM: out[m,k] = sqrt( (Axw@Bc)^2 + (Axw@Bs)^2 ),
// A scaling fused into the SMEM store. BMxBNxBK = 128x64x16, 256 thr, 8x4 tile.
// ---------------------------------------------------------------------------
__global__ void __launch_bounds__(THREADS, 2)
gemm_kernel(const float* __restrict__ x, float* __restrict__ out) {
    __shared__ float As[BM * 17];       // stride 17: conflict-free compute reads
    __shared__ float Bcs[BK * BN];
    __shared__ float Bss[BK * BN];

    const int tid = threadIdx.x;
    const int tx  = tid & 15;           // output-k block (x TN)
    const int ty  = tid >> 4;           // output-m block (x TM)
    const int m0  = blockIdx.y * BM;
    const int k0  = blockIdx.x * BN;

    // A staging: thread loads 8 floats of row (tid/2), col half (tid&1)*8
    const int ar = tid >> 1;
    const int aq = tid & 1;
    const int am = m0 + ar;
    const int ad = am & (D_ - 1);
    const float* xrow = x + (size_t)am * L_ + aq * 8;
    const float* srow = g_scale + (size_t)ad * L_ + aq * 8;

    // B staging: thread loads one float4 of each basis
    const int br = tid >> 4;
    const int bc = (tid & 15) * 4;
    const float* bcrow = g_Bc + (size_t)br * K_ + k0 + bc;
    const float* bsrow = g_Bs + (size_t)br * K_ + k0 + bc;

    unsigned long long accr[TM][TN/2];
    unsigned long long acci[TM][TN/2];
    #pragma unroll
    for (int i = 0; i < TM; i++)
        #pragma unroll
        for (int j = 0; j < TN/2; j++) { accr[i][j] = 0ull; acci[i][j] = 0ull; }

    // prefetch tile 0 into registers
    float4 xa0 = *(const float4*)(xrow + 0);
    float4 xa1 = *(const float4*)(xrow + 4);
    float4 sc0 = *(const float4*)(srow + 0);
    float4 sc1 = *(const float4*)(srow + 4);
    float4 bcv = *(const float4*)(bcrow);
    float4 bsv = *(const float4*)(bsrow);

    for (int t = 0; t < L_/BK; t++) {
        // commit staged tile to SMEM (scale fused here)
        {
            float va[8] = {xa0.x*sc0.x, xa0.y*sc0.y, xa0.z*sc0.z, xa0.w*sc0.w,
                           xa1.x*sc1.x, xa1.y*sc1.y, xa1.z*sc1.z, xa1.w*sc1.w};
            #pragma unroll
            for (int i = 0; i < 8; i++) As[ar*17 + aq*8 + i] = va[i];
            *(float4*)(&Bcs[br*BN + bc]) = bcv;
            *(float4*)(&Bss[br*BN + bc]) = bsv;
        }
        __syncthreads();

        // prefetch next tile (overlaps with compute below)
        if (t + 1 < L_/BK) {
            int off = (t + 1) * BK;
            xa0 = *(const float4*)(xrow + off);
            xa1 = *(const float4*)(xrow + off + 4);
            sc0 = *(const float4*)(srow + off);
            sc1 = *(const float4*)(srow + off + 4);
            bcv = *(const float4*)(bcrow + (size_t)off * K_);
            bsv = *(const float4*)(bsrow + (size_t)off * K_);
        }

        // compute: 16 k-steps, 32 FFMA2 per thread per step
        #pragma unroll
        for (int kk = 0; kk < BK; kk++) {
            unsigned long long a2[TM];
            #pragma unroll
            for (int i = 0; i < TM; i++) {
                float av = As[(ty*TM + i)*17 + kk];
                a2[i] = pack2(av, av);
            }
            ulonglong2 b2c = *(const ulonglong2*)(&Bcs[kk*BN + tx*TN]);
            ulonglong2 b2s = *(const ulonglong2*)(&Bss[kk*BN + tx*TN]);
            #pragma unroll
            for (int i = 0; i < TM; i++) {
                accr[i][0] = fma2(a2[i], b2c.x, accr[i][0]);
                accr[i][1] = fma2(a2[i], b2c.y, accr[i][1]);
                acci[i][0] = fma2(a2[i], b2s.x, acci[i][0]);
                acci[i][1] = fma2(a2[i], b2s.y, acci[i][1]);
            }
        }
        __syncthreads();
    }

    // epilogue: magnitude + vectorized store
    #pragma unroll
    for (int i = 0; i < TM; i++) {
        int m = m0 + ty*TM + i;
        float xr0, xr1, xi0, xi1;
        float4 o;
        unpack2(accr[i][0], xr0, xr1);
        unpack2(acci[i][0], xi0, xi1);
        o.x = sqrtf(xr0*xr0 + xi0*xi0);
        o.y = sqrtf(xr1*xr1 + xi1*xi1);
        unpack2(accr[i][1], xr0, xr1);
        unpack2(acci[i][1], xi0, xi1);
        o.z = sqrtf(xr0*xr0 + xi0*xi0);
        o.w = sqrtf(xr1*xr1 + xi1*xi1);
        *(float4*)(out + (size_t)m * K_ + k0 + tx*TN) = o;
    }
}

extern "C" void kernel_launch(void* const* d_in, const int* in_sizes, int n_in,
                              void* d_out, int out_size) {
    const float* x     = (const float*)d_in[0];   // (N, D, L)
    const float* a     = (const float*)d_in[1];   // (D,)
    const float* sigma = (const float*)d_in[2];   // (D,)
    float* out = (float*)d_out;                   // (N, D, K)

    prep_kernel<<<(L_*K_ + 255)/256, 256>>>(a, sigma);

    dim3 grid(K_/BN, M_/BM);   // (8, 512)
    gemm_kernel<<<grid, THREADS>>>(x, out);
}

// round 4
// speedup vs baseline: 1.2408x; 1.2408x over previous
#include <cuda_runtime.h>

#define N_ 128
#define D_ 512
#define L_ 512
#define K_ 512
#define KH 256            // half spectrum (mirror symmetry |X(511-k)|=|X(k)|)
#define M_ (N_*D_)        // 65536

#define BM 128
#define BN 64
#define BK 16
#define THREADS 256

// Static scratch (no runtime allocation)
__device__ float  g_scale[D_*L_];            // window*exp  [D][L]
__device__ float  g_xw[(size_t)M_ * L_];     // prescaled x [M][L]  (~134MB)
__device__ float2 g_Bc2[L_*KH];              // cos basis, duplicated pairs [L][KH]
__device__ float2 g_Bs2[L_*KH];              // sin basis, duplicated pairs [L][KH]

// ---------------------------------------------------------------------------
// Prep 1: per-(d,l) scale = (a - (1-a)cos(2*pi*l/511)) * exp(sigma/511)
// ---------------------------------------------------------------------------
__global__ void prep_scale(const float* __restrict__ a,
                           const float* __restrict__ sigma) {
    int idx = blockIdx.x * blockDim.x + threadIdx.x;
    if (idx >= D_*L_) return;
    int d = idx / L_;
    int l = idx % L_;
    const float TWOPI = 6.28318530717958647692f;
    float wang = __fdiv_rn((float)l * TWOPI, 511.0f);
    float wcos = (float)cos((double)wang);
    float ad   = a[d];
    float w    = ad - (1.0f - ad) * wcos;
    float e    = expf(__fdiv_rn(sigma[d], 511.0f));
    g_scale[idx] = w * e;
}

// ---------------------------------------------------------------------------
// Prep 2: xw = x * scale (vectorized float4)
// ---------------------------------------------------------------------------
__global__ void prep_xw(const float* __restrict__ x) {
    size_t i4 = (size_t)blockIdx.x * blockDim.x + threadIdx.x;   // float4 index
    size_t e  = i4 * 4;
    int m = (int)(e / L_);
    int l = (int)(e % L_);
    int d = m & (D_ - 1);
    float4 xv = *(const float4*)(x + e);
    float4 sv = *(const float4*)(g_scale + (size_t)d * L_ + l);
    float4 o;
    o.x = xv.x * sv.x; o.y = xv.y * sv.y; o.z = xv.z * sv.z; o.w = xv.w * sv.w;
    *(float4*)(g_xw + e) = o;
}

// ---------------------------------------------------------------------------
// Prep 3: DFT basis for k in [0, 256), stored as duplicated float2 pairs.
// Angle replicates reference fp32 rounding: fl(fl(2pi/511) * fl(l*k)).
// Double sincos: accuracy survives --use_fast_math at args ~3200 rad.
// ---------------------------------------------------------------------------
__global__ void prep_basis() {
    int idx = blockIdx.x * blockDim.x + threadIdx.x;
    if (idx >= L_*KH) return;
    int l = idx / KH;
    int k = idx % KH;
    const float TWOPI = 6.28318530717958647692f;
    float c0   = __fdiv_rn(TWOPI, 511.0f);
    float angf = c0 * (float)(l * k);
    double s, c;
    sincos((double)angf, &s, &c);
    g_Bc2[idx] = make_float2((float)c, (float)c);
    g_Bs2[idx] = make_float2((float)s, (float)s);
}

// ---------------------------------------------------------------------------
// f32x2 packed-FMA helpers
// ---------------------------------------------------------------------------
__device__ __forceinline__ void unpack2(unsigned long long v, float& x, float& y) {
    asm("mov.b64 {%0, %1}, %2;" : "=f"(x), "=f"(y) : "l"(v));
}
__device__ __forceinline__ unsigned long long fma2(unsigned long long a,
                                                   unsigned long long b,
                                                   unsigned long long c) {
    unsigned long long d;
    asm("fma.rn.f32x2 %0, %1, %2, %3;" : "=l"(d) : "l"(a), "l"(b), "l"(c));
    return d;
}

// ---------------------------------------------------------------------------
// GEMM: out[m,k] = sqrt((xw@Bc)^2 + (xw@Bs)^2) for k in [0,256),
// mirrored to out[m,511-k]. A in SMEM k-major (LDS.128 -> packed m-pairs),
// B pre-duplicated (LDS.128 -> packed splats). 6 LDS + 32 FFMA2 per k-step.
// ---------------------------------------------------------------------------
__global__ void __launch_bounds__(THREADS, 2)
gemm_kernel(float* __restrict__ out) {
    __shared__ __align__(16) float  As [BK * BM];   // [kk][m]
    __shared__ __align__(16) float2 Bcs[BK * BN];   // [kk][k] dup pairs
    __shared__ __align__(16) float2 Bss[BK * BN];

    const int tid = threadIdx.x;
    const int tx  = tid & 15;            // output k-quad (x4 cols)
    const int ty  = tid >> 4;            // output m-oct  (x8 rows)
    const int m0  = blockIdx.y * BM;
    const int k0  = blockIdx.x * BN;

    // A staging: thread t handles m = t&127, k-quads kq = (t>>7)*2 + {0,1}
    const int am = tid & 127;
    const int ak = (tid >> 7) * 2;
    const float* xwrow = g_xw + (size_t)(m0 + am) * L_;

    // B staging: slots s = tid, tid+256 -> row=s>>5, col4=s&31 (float4 units)
    const float4* bc4 = (const float4*)g_Bc2;
    const float4* bs4 = (const float4*)g_Bs2;
    const int brow0 = tid >> 5;            // rows 0..7  (slot tid)
    const int bcol0 = tid & 31;
    const int kof4  = k0 >> 1;             // k0 in float4 units of dup table

    unsigned long long accr[4][4];   // [m-pair][col]
    unsigned long long acci[4][4];
    #pragma unroll
    for (int i = 0; i < 4; i++)
        #pragma unroll
        for (int j = 0; j < 4; j++) { accr[i][j] = 0ull; acci[i][j] = 0ull; }

    // prefetch tile 0
    float4 pa0  = *(const float4*)(xwrow + (ak + 0) * 4);
    float4 pa1  = *(const float4*)(xwrow + (ak + 1) * 4);
    float4 pbc0 = bc4[(size_t)(brow0    ) * (KH/2) + kof4 + bcol0];
    float4 pbc1 = bc4[(size_t)(brow0 + 8) * (KH/2) + kof4 + bcol0];
    float4 pbs0 = bs4[(size_t)(brow0    ) * (KH/2) + kof4 + bcol0];
    float4 pbs1 = bs4[(size_t)(brow0 + 8) * (KH/2) + kof4 + bcol0];

    float4* Bcs4 = (float4*)Bcs;
    float4* Bss4 = (float4*)Bss;

    for (int t = 0; t < L_/BK; t++) {
        // commit staged tile
        As[(ak*4 + 0)*BM + am] = pa0.x;
        As[(ak*4 + 1)*BM + am] = pa0.y;
        As[(ak*4 + 2)*BM + am] = pa0.z;
        As[(ak*4 + 3)*BM + am] = pa0.w;
        As[(ak*4 + 4)*BM + am] = pa1.x;
        As[(ak*4 + 5)*BM + am] = pa1.y;
        As[(ak*4 + 6)*BM + am] = pa1.z;
        As[(ak*4 + 7)*BM + am] = pa1.w;
        Bcs4[brow0      *32 + bcol0] = pbc0;
        Bcs4[(brow0 + 8)*32 + bcol0] = pbc1;
        Bss4[brow0      *32 + bcol0] = pbs0;
        Bss4[(brow0 + 8)*32 + bcol0] = pbs1;
        __syncthreads();

        // prefetch next tile
        if (t + 1 < L_/BK) {
            int lof = (t + 1) * BK;
            pa0  = *(const float4*)(xwrow + lof + (ak + 0) * 4);
            pa1  = *(const float4*)(xwrow + lof + (ak + 1) * 4);
            pbc0 = bc4[(size_t)(lof + brow0    ) * (KH/2) + kof4 + bcol0];
            pbc1 = bc4[(size_t)(lof + brow0 + 8) * (KH/2) + kof4 + bcol0];
            pbs0 = bs4[(size_t)(lof + brow0    ) * (KH/2) + kof4 + bcol0];
            pbs1 = bs4[(size_t)(lof + brow0 + 8) * (KH/2) + kof4 + bcol0];
        }

        // 16 k-steps: 6 LDS.128 + 32 FFMA2 each
        #pragma unroll
        for (int kk = 0; kk < BK; kk++) {
            ulonglong2 a01 = *(const ulonglong2*)&As[kk*BM + ty*8];
            ulonglong2 a23 = *(const ulonglong2*)&As[kk*BM + ty*8 + 4];
            ulonglong2 bc0 = *(const ulonglong2*)&Bcs4[kk*32 + tx*2];
            ulonglong2 bc1 = *(const ulonglong2*)&Bcs4[kk*32 + tx*2 + 1];
            ulonglong2 bs0 = *(const ulonglong2*)&Bss4[kk*32 + tx*2];
            ulonglong2 bs1 = *(const ulonglong2*)&Bss4[kk*32 + tx*2 + 1];
            unsigned long long am_[4] = {a01.x, a01.y, a23.x, a23.y};
            #pragma unroll
            for (int i = 0; i < 4; i++) {
                accr[i][0] = fma2(am_[i], bc0.x, accr[i][0]);
                accr[i][1] = fma2(am_[i], bc0.y, accr[i][1]);
                accr[i][2] = fma2(am_[i], bc1.x, accr[i][2]);
                accr[i][3] = fma2(am_[i], bc1.y, accr[i][3]);
                acci[i][0] = fma2(am_[i], bs0.x, acci[i][0]);
                acci[i][1] = fma2(am_[i], bs0.y, acci[i][1]);
                acci[i][2] = fma2(am_[i], bs1.x, acci[i][2]);
                acci[i][3] = fma2(am_[i], bs1.y, acci[i][3]);
            }
        }
        __syncthreads();
    }

    // epilogue: magnitude, direct + mirrored stores
    const int c = k0 + tx * 4;          // direct base col (in [0,256))
    #pragma unroll
    for (int i = 0; i < 4; i++) {
        float lo[4], hi[4];
        #pragma unroll
        for (int j = 0; j < 4; j++) {
            float xr0, xr1, xi0, xi1;
            unpack2(accr[i][j], xr0, xr1);
            unpack2(acci[i][j], xi0, xi1);
            lo[j] = sqrtf(xr0*xr0 + xi0*xi0);
            hi[j] = sqrtf(xr1*xr1 + xi1*xi1);
        }
        int row0 = m0 + ty*8 + 2*i;
        int row1 = row0 + 1;
        float4 v0  = make_float4(lo[0], lo[1], lo[2], lo[3]);
        float4 v0r = make_float4(lo[3], lo[2], lo[1], lo[0]);
        float4 v1  = make_float4(hi[0], hi[1], hi[2], hi[3]);
        float4 v1r = make_float4(hi[3], hi[2], hi[1], hi[0]);
        *(float4*)(out + (size_t)row0 * K_ + c)           = v0;
        *(float4*)(out + (size_t)row0 * K_ + (508 - c))   = v0r;   // cols 511-k
        *(float4*)(out + (size_t)row1 * K_ + c)           = v1;
        *(float4*)(out + (size_t)row1 * K_ + (508 - c))   = v1r;
    }
}

extern "C" void kernel_launch(void* const* d_in, const int* in_sizes, int n_in,
                              void* d_out, int out_size) {
    const float* x     = (const float*)d_in[0];   // (N, D, L)
    const float* a     = (const float*)d_in[1];   // (D,)
    const float* sigma = (const float*)d_in[2];   // (D,)
    float* out = (float*)d_out;                   // (N, D, K)

    prep_scale<<<(D_*L_ + 255)/256, 256>>>(a, sigma);
    prep_xw<<<(int)(((size_t)M_*L_/4 + 255)/256), 256>>>(x);
    prep_basis<<<(L_*KH + 255)/256, 256>>>();

    dim3 grid(KH/BN, M_/BM);   // (4, 512)
    gemm_kernel<<<grid, THREADS>>>(out);
}